// round 1
// baseline (speedup 1.0000x reference)
#include <cuda_runtime.h>

#define NUM_C 64
#define FD    128
#define BLK_T 128
#define TROWS 256
#define UNR   16
#define GRID_MAIN 592
#define N_PAIRS (NUM_C * (NUM_C - 1) / 2)   // 2016

__device__ float g_sums[NUM_C * FD];
__device__ int   g_counts[NUM_C];
__device__ float g_sumsq;

__global__ void zero_k() {
    int i = blockIdx.x * blockDim.x + threadIdx.x;
    if (i < NUM_C * FD) g_sums[i] = 0.0f;
    if (i < NUM_C) g_counts[i] = 0;
    if (i == 0) g_sumsq = 0.0f;
}

__global__ __launch_bounds__(BLK_T) void accum_k(const float* __restrict__ feat,
                                                 const int* __restrict__ tgt,
                                                 int B) {
    __shared__ float acc[NUM_C * FD];   // thread t owns column t exclusively
    __shared__ int   scnt[NUM_C];
    __shared__ int   stgt[TROWS];

    int tid = threadIdx.x;
    for (int i = tid; i < NUM_C * FD; i += BLK_T) acc[i] = 0.0f;
    if (tid < NUM_C) scnt[tid] = 0;
    __syncthreads();

    int per = (B + gridDim.x - 1) / gridDim.x;
    int r0 = blockIdx.x * per;
    int r1 = min(r0 + per, B);

    float sq = 0.0f;
    for (int base = r0; base < r1; base += TROWS) {
        int n = min(TROWS, r1 - base);
        __syncthreads();   // previous chunk's compute done before stgt overwrite
        for (int i = tid; i < n; i += BLK_T) {
            int t = tgt[base + i];
            stgt[i] = t;
            atomicAdd(&scnt[t], 1);
        }
        __syncthreads();

        int u = 0;
        for (; u + UNR <= n; u += UNR) {
            float v[UNR];
#pragma unroll
            for (int k = 0; k < UNR; k++)
                v[k] = feat[(base + u + k) * FD + tid];
#pragma unroll
            for (int k = 0; k < UNR; k++) {
                int c = stgt[u + k];
                acc[c * FD + tid] += v[k];
                sq += v[k] * v[k];
            }
        }
        for (; u < n; u++) {
            float v = feat[(base + u) * FD + tid];
            int c = stgt[u];
            acc[c * FD + tid] += v;
            sq += v * v;
        }
    }
    __syncthreads();

    // flush block partials
    for (int i = tid; i < NUM_C * FD; i += BLK_T) atomicAdd(&g_sums[i], acc[i]);
    if (tid < NUM_C) atomicAdd(&g_counts[tid], scnt[tid]);
#pragma unroll
    for (int o = 16; o > 0; o >>= 1) sq += __shfl_down_sync(0xffffffffu, sq, o);
    if ((tid & 31) == 0) atomicAdd(&g_sumsq, sq);
}

__global__ __launch_bounds__(256) void epi_k(float* __restrict__ out, int B) {
    __shared__ float cent[NUM_C * FD];
    __shared__ float ired[8];
    __shared__ float hred[8];

    int tid = threadIdx.x;
    int wid = tid >> 5, lane = tid & 31;

    // centers + Sum_c cnt_c * ||center_c||^2 = Sum_i S_i * center_i
    float ipart = 0.0f;
    for (int i = tid; i < NUM_C * FD; i += 256) {
        int c = i >> 7;
        float cnt = fmaxf((float)g_counts[c], 1.0f);
        float s = g_sums[i];
        float ce = s / cnt;
        cent[i] = ce;
        ipart += s * ce;
    }
#pragma unroll
    for (int o = 16; o > 0; o >>= 1) ipart += __shfl_down_sync(0xffffffffu, ipart, o);
    if (lane == 0) ired[wid] = ipart;
    __syncthreads();

    // pairwise hinge: one (i,j) pair per warp iteration, lanes cover 128 dims (float4)
    float hsum = 0.0f;
    for (int i = wid; i < NUM_C - 1; i += 8) {
        const float4* ci = (const float4*)&cent[i * FD];
        float4 a = ci[lane];
        for (int j = i + 1; j < NUM_C; j++) {
            const float4* cj = (const float4*)&cent[j * FD];
            float4 b = cj[lane];
            float dx = a.x - b.x, dy = a.y - b.y, dz = a.z - b.z, dw = a.w - b.w;
            float d2 = dx * dx + dy * dy + dz * dz + dw * dw;
#pragma unroll
            for (int o = 16; o > 0; o >>= 1) d2 += __shfl_down_sync(0xffffffffu, d2, o);
            if (lane == 0) {
                float w = (i == 1 && j == 2) ? 2.0f : 1.0f;
                hsum += w * fmaxf(2.0f - d2, 0.0f);   // MARGIN = 2
            }
        }
    }
    if (lane == 0) hred[wid] = hsum;
    __syncthreads();

    if (tid == 0) {
        float isum = 0.0f, hs = 0.0f;
#pragma unroll
        for (int k = 0; k < 8; k++) { isum += ired[k]; hs += hred[k]; }
        float intra = (g_sumsq - isum) / (float)B;
        float inter = hs / (float)N_PAIRS;
        out[0] = intra + inter;   // LAMBDA_INTRA = LAMBDA_INTER = 1
    }
}

extern "C" void kernel_launch(void* const* d_in, const int* in_sizes, int n_in,
                              void* d_out, int out_size) {
    const float* feat = (const float*)d_in[0];
    const int*   tgt  = (const int*)d_in[1];
    int B = in_sizes[1];

    zero_k<<<(NUM_C * FD + 255) / 256, 256>>>();
    accum_k<<<GRID_MAIN, BLK_T>>>(feat, tgt, B);
    epi_k<<<1, 256>>>((float*)d_out, B);
}